// round 14
// baseline (speedup 1.0000x reference)
#include <cuda_runtime.h>
#include <math.h>

#define BB   16
#define LL   4096
#define DD   512
#define LP1  4097
#define D4   128        // D/4 float4 lanes per row
#define CH   8          // l rows per chunk
#define NT   256        // threads per block
#define BG   2          // batch elements per block (BB/BG b-groups)

// ---------------------------------------------------------------------------
// freq[d] = 100^(-(d - d%2)/512) = r^(d>>1), r = 100^(-1/256), via binary
// exponentiation in double (pure DMUL, ~2.5e-10 rel err, below f32 ulp).
// ---------------------------------------------------------------------------
__device__ __forceinline__ float freq_of(int d) {
    const double R = 0.982171889188039;   // 100^(-1/256)
    double f = 1.0, p = R;
    int k = d >> 1;                        // 0..255
#pragma unroll
    for (int i = 0; i < 8; i++) {
        if (k & 1) f *= p;
        p *= p;
        k >>= 1;
    }
    return (float)f;
}

// sin/cos for x in (0, 1.01] — no range reduction, Taylor, abs err < 3e-6.
__device__ __forceinline__ void sincos_small(float x, float* s, float* c) {
    float x2 = x * x;
    *s = x * fmaf(x2, fmaf(x2, fmaf(x2, -1.9841270e-4f, 8.3333333e-3f),
                           -0.16666667f), 1.0f);
    *c = fmaf(x2, fmaf(x2, fmaf(x2, fmaf(x2, 2.4801587e-5f, -1.3888889e-3f),
                                4.1666667e-2f), -0.5f), 1.0f);
}

// ---------------------------------------------------------------------------
// Fused kernel. Grid = 512 l-chunks x 8 b-groups + 1 epilogue = 4097 CTAs.
//   Phase 1: build emb rows [l0, l0+8) in smem. Per d-lane: ONE sincosf
//            anchor at l0*c (large arg), polynomial sincos for the step
//            rotation (c in range), then 8-step angle-addition recurrence.
//   Phase 2: stream BG=2 batch elements; per-b loads batched 4-deep (MLP 4).
//  Last block: the 16 rows at l = 4096 (cls or zero only).
// ---------------------------------------------------------------------------
__global__ void __launch_bounds__(NT, 8)
fused_kernel(const float4* __restrict__ tok,
             const int*    __restrict__ lengths,
             const float4* __restrict__ cls,
             float4*       __restrict__ out)
{
    int t    = threadIdx.x;
    int d4   = t & (D4 - 1);               // 0..127
    int slot = t >> 7;                     // 0..1
    float4 clsv = __ldg(&cls[d4]);
    const float4 zero = make_float4(0.f, 0.f, 0.f, 0.f);

    if (blockIdx.x == (LL / CH) * (BB / BG)) {   // ---- epilogue: l = LL ----
#pragma unroll
        for (int i = 0; i < BB / 2; i++) {
            int b = i * 2 + slot;
            int len = __ldg(&lengths[b]);
            float4 v = (len == LL) ? clsv : zero;
            __stcs(&out[((size_t)b * LP1 + LL) * D4 + d4], v);
        }
        return;
    }

    __shared__ float s_emb[CH * DD];       // 16 KB
    __shared__ int   s_len[BG];

    int chunk = blockIdx.x >> 3;           // 0..511
    int bg    = blockIdx.x & 7;            // 0..7
    int l0    = chunk * CH;
    int bbase = bg * BG;

    // ---- phase 1: emb rows for this chunk (2 d-lanes per thread) ----
#pragma unroll
    for (int h = 0; h < 2; h++) {
        int d = t + h * NT;
        float f = freq_of(d);
        int  odd = d & 1;
        float c  = f + (odd ? 1.57079632679489662f : 0.0f);

        // step rotation by c: (sin c, cos c) from in-range sincos of f
        float sf, cf;
        sincos_small(f, &sf, &cf);
        float sd = odd ? cf : sf;
        float cd = odd ? -sf : cf;

        // anchor: sin/cos(l0 * c) — large arg, needs libm range reduction
        float s, cs;
        sincosf((float)l0 * c, &s, &cs);

#pragma unroll
        for (int k = 0; k < CH; k++) {
            s_emb[k * DD + d] = s;
            float ns = fmaf(s,  cd, cs * sd);
            float nc = fmaf(cs, cd, -(s * sd));
            s = ns; cs = nc;
        }
    }
    if (t < BG) s_len[t] = lengths[bbase + t];
    __syncthreads();

    // ---- phase 2: stream BG batch elements, 4 loads in flight per b ----
    const float4* se = reinterpret_cast<const float4*>(s_emb);

#pragma unroll 1
    for (int u = 0; u < BG; u++) {
        int b    = bbase + u;
        int lrel = s_len[u] - l0;          // rows with ll < lrel are valid
        const float4* tp = &tok[((size_t)b * LL  + l0) * D4 + d4];
        float4*       op = &out[((size_t)b * LP1 + l0) * D4 + d4];

        float4 tk[4];
#pragma unroll
        for (int j = 0; j < 4; j++) {
            int ll = slot + j * 2;
            if (ll < lrel)
                tk[j] = tp[ll * D4];
        }
#pragma unroll
        for (int j = 0; j < 4; j++) {
            int ll = slot + j * 2;
            float4 v;
            if (ll < lrel) {
                float4 em = se[ll * D4 + d4];
                v.x = tk[j].x + em.x;
                v.y = tk[j].y + em.y;
                v.z = tk[j].z + em.z;
                v.w = tk[j].w + em.w;
            } else {
                v = (ll == lrel) ? clsv : zero;
            }
            __stcs(&op[ll * D4], v);
        }
    }
}

// ---------------------------------------------------------------------------
extern "C" void kernel_launch(void* const* d_in, const int* in_sizes, int n_in,
                              void* d_out, int out_size)
{
    const float4* tok     = (const float4*)d_in[0];   // tokens  [B,L,D] f32
    const int*    lengths = (const int*)   d_in[1];   // lengths [B]    i32
    const float4* cls     = (const float4*)d_in[2];   // cls     [D]    f32
    float4*       out     = (float4*)d_out;           // [B,L+1,D] f32

    fused_kernel<<<(LL / CH) * (BB / BG) + 1, NT>>>(tok, lengths, cls, out);
}